// round 1
// baseline (speedup 1.0000x reference)
#include <cuda_runtime.h>
#include <math.h>

// Problem constants (fixed shapes per reference)
#define N_TOK 49
#define C_DIM 128
#define H_NUM 4
#define HD    32

// Shared-memory layout (float offsets)
// region1: xs [56][128] = 7168 floats  (phase A)  -- reused as attn [4][49][49] = 9604 floats
#define R1_SIZE   9604
#define QS_OFF    (R1_SIZE)            // q: [4][49][32] = 6272 (reused as ao [49][128] in phase D/E)
#define KS_OFF    (QS_OFF + 6272)      // k: [4][49][34] = 6664 (pad-34 for conflict-free float2 LDS)
#define VS_OFF    (KS_OFF + 6664)      // v: [4][49][32] = 6272
#define SMEM_FLOATS (VS_OFF + 6272)    // 28812 floats = 115248 bytes -> 2 CTAs/SM

__global__ __launch_bounds__(256, 2)
void win_attn_kernel(const float* __restrict__ x,
                     const float* __restrict__ mask,
                     const float* __restrict__ qkv_w,
                     const float* __restrict__ qkv_b,
                     const float* __restrict__ proj_w,
                     const float* __restrict__ proj_b,
                     const float* __restrict__ bias_tab,
                     float* __restrict__ out)
{
    extern __shared__ float sm[];
    float* xs   = sm;             // [56][128]
    float* attn = sm;             // [4][49][49] (after xs is dead)
    float* qs   = sm + QS_OFF;    // [4][49][32]
    float* ks   = sm + KS_OFF;    // [4][49][34]
    float* vs   = sm + VS_OFF;    // [4][49][32]

    const int b    = blockIdx.x;
    const int tid  = threadIdx.x;
    const int lane = tid & 31;
    const int warp = tid >> 5;

    // ---- Load x tile (49x128), zero-pad rows 49..55 ----
    {
        const float4* xg  = (const float4*)(x + (size_t)b * 6272);
        float4*       xs4 = (float4*)xs;
        for (int i = tid; i < 1568; i += 256) xs4[i] = xg[i];
        for (int i = 6272 + tid; i < 7168; i += 256) xs[i] = 0.f;
    }
    __syncthreads();

    // ---- Phase A: QKV = x @ qkv_w + qkv_b ----
    // thread owns cols {c0, c0+128, c0+256} (one q / one k / one v col) x 28 rows.
    {
        const int c0   = tid & 127;
        const int row0 = (tid >> 7) * 28;   // 0 or 28 (rows padded to 56)
        const float bq = qkv_b[c0];
        const float bk = qkv_b[c0 + 128];
        const float bv = qkv_b[c0 + 256];

        float acc0[28], acc1[28], acc2[28];
        #pragma unroll
        for (int r = 0; r < 28; r++) { acc0[r] = 0.f; acc1[r] = 0.f; acc2[r] = 0.f; }

        const float* W = qkv_w + c0;
        #pragma unroll 2
        for (int k = 0; k < 128; k++) {
            const float w0 = W[k * 384];
            const float w1 = W[k * 384 + 128];
            const float w2 = W[k * 384 + 256];
            const float* xrow = xs + row0 * 128 + k;   // broadcast across warp lanes
            #pragma unroll
            for (int r = 0; r < 28; r++) {
                const float xv = xrow[r * 128];
                acc0[r] += xv * w0;
                acc1[r] += xv * w1;
                acc2[r] += xv * w2;
            }
        }

        const int h = c0 >> 5, d = c0 & 31;
        const float scale = 0.17677669529663687f;   // 1/sqrt(32)
        #pragma unroll
        for (int r = 0; r < 28; r++) {
            const int n = row0 + r;
            if (n < 49) {
                qs[h * 1568 + n * 32 + d] = (acc0[r] + bq) * scale;
                ks[h * 1666 + n * 34 + d] = acc1[r] + bk;
                vs[h * 1568 + n * 32 + d] = acc2[r] + bv;
            }
        }
    }
    __syncthreads();

    // ---- Phase B+C: scores + rel-bias + mask + softmax (fused, per (h,i) row per warp) ----
    {
        const int   wmask = b & 63;                  // window index for mask
        const int   j1 = lane;                       // always < 49
        const int   j2 = lane + 32;
        const bool  has2 = (j2 < 49);
        const float* mbase = mask + wmask * 2401;

        for (int flat = warp; flat < 196; flat += 8) {
            const int h = flat / 49;
            const int i = flat - h * 49;

            const float* qrow = qs + h * 1568 + i * 32;
            const float* k1p  = ks + h * 1666 + j1 * 34;
            const float* k2p  = k1p + 32 * 34;

            float a1 = 0.f, a2 = 0.f;
            #pragma unroll
            for (int d = 0; d < 32; d += 2) {
                const float2 qv  = *(const float2*)(qrow + d);   // broadcast
                const float2 kv1 = *(const float2*)(k1p + d);
                a1 += qv.x * kv1.x;
                a1 += qv.y * kv1.y;
                if (has2) {
                    const float2 kv2 = *(const float2*)(k2p + d);
                    a2 += qv.x * kv2.x;
                    a2 += qv.y * kv2.y;
                }
            }

            // relative position bias + attention mask
            const int ih = i / 7, iw = i - ih * 7;
            {
                const int jh = j1 / 7, jw = j1 - jh * 7;
                const int ridx = (ih - jh + 6) * 13 + (iw - jw + 6);
                a1 += bias_tab[ridx * 4 + h] + mbase[i * 49 + j1];
            }
            if (has2) {
                const int jh = j2 / 7, jw = j2 - jh * 7;
                const int ridx = (ih - jh + 6) * 13 + (iw - jw + 6);
                a2 += bias_tab[ridx * 4 + h] + mbase[i * 49 + j2];
            } else {
                a2 = -1e30f;
            }

            // softmax over the 49-long row (held in 49 of the 64 lane-slots)
            float m = fmaxf(a1, a2);
            #pragma unroll
            for (int o = 16; o > 0; o >>= 1) m = fmaxf(m, __shfl_xor_sync(0xffffffffu, m, o));
            const float e1 = __expf(a1 - m);
            const float e2 = has2 ? __expf(a2 - m) : 0.f;
            float s = e1 + e2;
            #pragma unroll
            for (int o = 16; o > 0; o >>= 1) s += __shfl_xor_sync(0xffffffffu, s, o);
            const float inv = 1.f / s;

            attn[h * 2401 + i * 49 + j1] = e1 * inv;
            if (has2) attn[h * 2401 + i * 49 + j2] = e2 * inv;
        }
    }
    __syncthreads();

    // ---- Phase D: ao = attn @ v  (ao overwrites qs region, layout [49][128]) ----
    {
        float* ao = qs;
        const int h     = warp & 3;
        const int ihalf = warp >> 2;
        const int i0 = ihalf * 25;
        const int i1 = ihalf ? 49 : 25;
        const int d  = lane;
        const float* vbase = vs + h * 1568 + d;
        const float* abase = attn + h * 2401;

        for (int i = i0; i < i1; i += 4) {
            float a0 = 0.f, a1 = 0.f, a2 = 0.f, a3 = 0.f;
            const int rem = i1 - i;
            const float* ar0 = abase + i * 49;
            for (int j = 0; j < 49; j++) {
                const float vv = vbase[j * 32];          // lanes = d, conflict-free
                a0 += ar0[j] * vv;                       // broadcast LDS
                if (rem > 1) a1 += ar0[49  + j] * vv;
                if (rem > 2) a2 += ar0[98  + j] * vv;
                if (rem > 3) a3 += ar0[147 + j] * vv;
            }
            ao[i * 128 + h * 32 + d] = a0;
            if (rem > 1) ao[(i + 1) * 128 + h * 32 + d] = a1;
            if (rem > 2) ao[(i + 2) * 128 + h * 32 + d] = a2;
            if (rem > 3) ao[(i + 3) * 128 + h * 32 + d] = a3;
        }
    }
    __syncthreads();

    // ---- Phase E: out = ao @ proj_w + proj_b ----
    // thread owns 2 cols x 14 rows (rows padded to 56; rows >= 49 discarded).
    {
        const float* ao  = qs;
        const int c2   = (tid & 63) * 2;
        const int row0 = (tid >> 6) * 14;

        float accx[14], accy[14];
        #pragma unroll
        for (int r = 0; r < 14; r++) { accx[r] = 0.f; accy[r] = 0.f; }

        const float* W = proj_w + c2;
        #pragma unroll 2
        for (int cc = 0; cc < 128; cc++) {
            const float2 wv = *(const float2*)(W + cc * 128);
            const float* arow = ao + row0 * 128 + cc;    // broadcast across warp
            #pragma unroll
            for (int r = 0; r < 14; r++) {
                const float xv = arow[r * 128];
                accx[r] += xv * wv.x;
                accy[r] += xv * wv.y;
            }
        }

        const float pbx = proj_b[c2];
        const float pby = proj_b[c2 + 1];
        float* ob = out + (size_t)b * 6272;
        #pragma unroll
        for (int r = 0; r < 14; r++) {
            const int n = row0 + r;
            if (n < 49) {
                float2 val = make_float2(accx[r] + pbx, accy[r] + pby);
                *(float2*)(ob + n * 128 + c2) = val;
            }
        }
    }
}

extern "C" void kernel_launch(void* const* d_in, const int* in_sizes, int n_in,
                              void* d_out, int out_size)
{
    const float* x        = (const float*)d_in[0];
    const float* mask     = (const float*)d_in[1];
    const float* qkv_w    = (const float*)d_in[2];
    const float* qkv_b    = (const float*)d_in[3];
    const float* proj_w   = (const float*)d_in[4];
    const float* proj_b   = (const float*)d_in[5];
    const float* bias_tab = (const float*)d_in[6];
    float* out = (float*)d_out;

    const int B = in_sizes[0] / (N_TOK * C_DIM);   // 4096

    cudaFuncSetAttribute(win_attn_kernel,
                         cudaFuncAttributeMaxDynamicSharedMemorySize,
                         SMEM_FLOATS * (int)sizeof(float));

    win_attn_kernel<<<B, 256, SMEM_FLOATS * sizeof(float)>>>(
        x, mask, qkv_w, qkv_b, proj_w, proj_b, bias_tab, out);
}

// round 2
// speedup vs baseline: 2.5534x; 2.5534x over previous
#include <cuda_runtime.h>

// smem word offsets (4-byte words). All matrices hold tf32 bit patterns.
#define QOFF 0           // Q [4][64][36]
#define KOFF 9216        // K [4][56][36]
#define VOFF 17280       // V [4][56][40]
#define XOFF 26240       // X / AO [64][132]
#define SMEM_WORDS 34688 // 138752 bytes -> 1 CTA/SM
// P overlays Q+K: [4][64][60] = 15360 words <= 17280

__device__ unsigned g_wqkv[128 * 384];
__device__ unsigned g_wproj[128 * 128];
__device__ float    g_fused[64 * 4 * 49 * 56];  // mask + rel_bias, j<49 filled

__device__ __forceinline__ unsigned f2tf(float f) {
    unsigned r; asm("cvt.rna.tf32.f32 %0, %1;" : "=r"(r) : "f"(f)); return r;
}
__device__ __forceinline__ void mma8(float* d, const unsigned* a, const unsigned* b) {
    asm volatile("mma.sync.aligned.m16n8k8.row.col.f32.tf32.tf32.f32 "
                 "{%0,%1,%2,%3},{%4,%5,%6,%7},{%8,%9},{%0,%1,%2,%3};"
                 : "+f"(d[0]), "+f"(d[1]), "+f"(d[2]), "+f"(d[3])
                 : "r"(a[0]), "r"(a[1]), "r"(a[2]), "r"(a[3]), "r"(b[0]), "r"(b[1]));
}

__global__ void prep_kernel(const float* __restrict__ mask,
                            const float* __restrict__ bias_tab,
                            const float* __restrict__ qkv_w,
                            const float* __restrict__ proj_w) {
    const int stride = gridDim.x * blockDim.x;
    const int t0 = blockIdx.x * blockDim.x + threadIdx.x;
    for (int i = t0; i < 128 * 384; i += stride) g_wqkv[i] = f2tf(qkv_w[i]);
    for (int i = t0; i < 128 * 128; i += stride) g_wproj[i] = f2tf(proj_w[i]);
    for (int e = t0; e < 64 * 4 * 49 * 49; e += stride) {
        int j = e % 49; int t = e / 49; int i = t % 49; t /= 49;
        int h = t & 3;  int w = t >> 2;
        int ih = i / 7, iw = i - ih * 7, jh = j / 7, jw = j - jh * 7;
        int ridx = (ih - jh + 6) * 13 + (iw - jw + 6);
        g_fused[((w * 4 + h) * 49 + i) * 56 + j] =
            mask[w * 2401 + i * 49 + j] + bias_tab[ridx * 4 + h];
    }
}

__global__ __launch_bounds__(256, 1)
void win_attn_mma(const float* __restrict__ x,
                  const float* __restrict__ qkv_b,
                  const float* __restrict__ proj_b,
                  float* __restrict__ out)
{
    extern __shared__ unsigned sm[];
    const int b = blockIdx.x, tid = threadIdx.x, lane = tid & 31, warp = tid >> 5;
    const int g = lane >> 2, tg = lane & 3;

    // ---- zero pad rows (49..) of Q/K/V/X ----
    for (int i = tid; i < 2160; i += 256) { int d = i % 36, t = i / 36, r = 49 + t % 15, h = t / 15; sm[QOFF + (h * 64 + r) * 36 + d] = 0; }
    for (int i = tid; i < 1008; i += 256) { int d = i % 36, t = i / 36, r = 49 + t % 7,  h = t / 7;  sm[KOFF + (h * 56 + r) * 36 + d] = 0; }
    for (int i = tid; i < 1120; i += 256) { int d = i % 40, t = i / 40, r = 49 + t % 7,  h = t / 7;  sm[VOFF + (h * 56 + r) * 40 + d] = 0; }
    for (int i = tid; i < 1980; i += 256) sm[XOFF + 49 * 132 + i] = 0;
    // ---- load x -> X (tf32) ----
    const float* xg = x + (size_t)b * 6272;
    for (int i = tid; i < 6272; i += 256) { int r = i >> 7, c = i & 127; sm[XOFF + r * 132 + c] = f2tf(xg[i]); }
    __syncthreads();

    // ================= Phase A: QKV = X @ Wqkv =================
    {
        float acc[4][6][4];
        #pragma unroll
        for (int mt = 0; mt < 4; mt++)
            #pragma unroll
            for (int nt = 0; nt < 6; nt++)
                #pragma unroll
                for (int c = 0; c < 4; c++) acc[mt][nt][c] = 0.f;

        const int colbase = warp * 48;
        unsigned bc[6][2];
        #pragma unroll
        for (int nt = 0; nt < 6; nt++) {
            int col = colbase + nt * 8 + g;
            bc[nt][0] = g_wqkv[tg * 384 + col];
            bc[nt][1] = g_wqkv[(tg + 4) * 384 + col];
        }
        #pragma unroll
        for (int kt = 0; kt < 16; kt++) {
            unsigned bn[6][2];
            if (kt < 15) {
                int k0 = (kt + 1) * 8;
                #pragma unroll
                for (int nt = 0; nt < 6; nt++) {
                    int col = colbase + nt * 8 + g;
                    bn[nt][0] = g_wqkv[(k0 + tg) * 384 + col];
                    bn[nt][1] = g_wqkv[(k0 + tg + 4) * 384 + col];
                }
            }
            unsigned a[4][4];
            const unsigned* X = sm + XOFF + kt * 8;
            #pragma unroll
            for (int mt = 0; mt < 4; mt++) {
                int r = mt * 16 + g;
                a[mt][0] = X[r * 132 + tg];       a[mt][1] = X[(r + 8) * 132 + tg];
                a[mt][2] = X[r * 132 + tg + 4];   a[mt][3] = X[(r + 8) * 132 + tg + 4];
            }
            #pragma unroll
            for (int mt = 0; mt < 4; mt++)
                #pragma unroll
                for (int nt = 0; nt < 6; nt++) mma8(acc[mt][nt], a[mt], bc[nt]);
            if (kt < 15) {
                #pragma unroll
                for (int nt = 0; nt < 6; nt++) { bc[nt][0] = bn[nt][0]; bc[nt][1] = bn[nt][1]; }
            }
        }
        // epilogue: +bias, scale q, scatter to Q/K/V smem as tf32
        const float scale = 0.17677669529663687f;
        #pragma unroll
        for (int mt = 0; mt < 4; mt++)
            #pragma unroll
            for (int hc = 0; hc < 2; hc++) {
                int row = mt * 16 + g + hc * 8;
                if (row < 49) {
                    #pragma unroll
                    for (int nt = 0; nt < 6; nt++) {
                        int G = colbase + nt * 8 + 2 * tg;
                        float v0 = acc[mt][nt][hc * 2]     + qkv_b[G];
                        float v1 = acc[mt][nt][hc * 2 + 1] + qkv_b[G + 1];
                        int part = G >> 7, cc = G & 127, h = cc >> 5, d = cc & 31;
                        uint2 pv;
                        if (part == 0) {
                            pv.x = f2tf(v0 * scale); pv.y = f2tf(v1 * scale);
                            *(uint2*)&sm[QOFF + (h * 64 + row) * 36 + d] = pv;
                        } else if (part == 1) {
                            pv.x = f2tf(v0); pv.y = f2tf(v1);
                            *(uint2*)&sm[KOFF + (h * 56 + row) * 36 + d] = pv;
                        } else {
                            pv.x = f2tf(v0); pv.y = f2tf(v1);
                            *(uint2*)&sm[VOFF + (h * 56 + row) * 40 + d] = pv;
                        }
                    }
                }
            }
    }
    __syncthreads();

    // ================= Phase S: scores + softmax (in regs) =================
    const int h = warp >> 1, mh = warp & 1;
    float sacc[2][7][4];
    {
        #pragma unroll
        for (int m = 0; m < 2; m++)
            #pragma unroll
            for (int n = 0; n < 7; n++)
                #pragma unroll
                for (int c = 0; c < 4; c++) sacc[m][n][c] = 0.f;
        #pragma unroll
        for (int kt = 0; kt < 4; kt++) {
            unsigned a[2][4], bb[7][2];
            const unsigned* Qb = sm + QOFF + h * 64 * 36 + kt * 8;
            #pragma unroll
            for (int m = 0; m < 2; m++) {
                int r = (mh * 2 + m) * 16 + g;
                a[m][0] = Qb[r * 36 + tg];       a[m][1] = Qb[(r + 8) * 36 + tg];
                a[m][2] = Qb[r * 36 + tg + 4];   a[m][3] = Qb[(r + 8) * 36 + tg + 4];
            }
            const unsigned* Kb = sm + KOFF + h * 56 * 36 + kt * 8;
            #pragma unroll
            for (int n = 0; n < 7; n++) {
                int nn = n * 8 + g;
                bb[n][0] = Kb[nn * 36 + tg]; bb[n][1] = Kb[nn * 36 + tg + 4];
            }
            #pragma unroll
            for (int m = 0; m < 2; m++)
                #pragma unroll
                for (int n = 0; n < 7; n++) mma8(sacc[m][n], a[m], bb[n]);
        }
        const float* fus = g_fused + (((b & 63) * 4 + h) * 49) * 56;
        #pragma unroll
        for (int m = 0; m < 2; m++)
            #pragma unroll
            for (int hc = 0; hc < 2; hc++) {
                int row = (mh * 2 + m) * 16 + g + hc * 8;
                float vals[14]; float vmax = -1e30f;
                #pragma unroll
                for (int n = 0; n < 7; n++) {
                    int j = n * 8 + 2 * tg;
                    float f0 = 0.f, f1 = 0.f;
                    if (row < 49) {
                        float2 fv = *(const float2*)&fus[row * 56 + j];
                        f0 = fv.x; f1 = fv.y;
                    }
                    float v0 = (j < 49)     ? sacc[m][n][hc * 2]     + f0 : -1e30f;
                    float v1 = (j + 1 < 49) ? sacc[m][n][hc * 2 + 1] + f1 : -1e30f;
                    if (row >= 49) { v0 = (j < 49) ? 0.f : -1e30f; v1 = (j + 1 < 49) ? 0.f : -1e30f; }
                    vals[2 * n] = v0; vals[2 * n + 1] = v1;
                    vmax = fmaxf(vmax, fmaxf(v0, v1));
                }
                vmax = fmaxf(vmax, __shfl_xor_sync(0xffffffffu, vmax, 1));
                vmax = fmaxf(vmax, __shfl_xor_sync(0xffffffffu, vmax, 2));
                float s = 0.f;
                #pragma unroll
                for (int t = 0; t < 14; t++) { vals[t] = __expf(vals[t] - vmax); s += vals[t]; }
                s += __shfl_xor_sync(0xffffffffu, s, 1);
                s += __shfl_xor_sync(0xffffffffu, s, 2);
                float inv = 1.f / s;
                #pragma unroll
                for (int n = 0; n < 7; n++) {
                    sacc[m][n][hc * 2]     = vals[2 * n] * inv;
                    sacc[m][n][hc * 2 + 1] = vals[2 * n + 1] * inv;
                }
            }
    }
    __syncthreads();   // all warps done reading Q/K before P overlays them
    {
        #pragma unroll
        for (int m = 0; m < 2; m++)
            #pragma unroll
            for (int hc = 0; hc < 2; hc++) {
                int row = (mh * 2 + m) * 16 + g + hc * 8;
                #pragma unroll
                for (int n = 0; n < 7; n++) {
                    uint2 pv;
                    pv.x = f2tf(sacc[m][n][hc * 2]);
                    pv.y = f2tf(sacc[m][n][hc * 2 + 1]);
                    *(uint2*)&sm[(h * 64 + row) * 60 + n * 8 + 2 * tg] = pv;
                }
            }
    }
    __syncthreads();

    // ================= Phase AV: AO = P @ V =================
    {
        float av[2][4][4];
        #pragma unroll
        for (int m = 0; m < 2; m++)
            #pragma unroll
            for (int n = 0; n < 4; n++)
                #pragma unroll
                for (int c = 0; c < 4; c++) av[m][n][c] = 0.f;
        #pragma unroll
        for (int kt = 0; kt < 7; kt++) {
            unsigned a[2][4], bb[4][2];
            const unsigned* Pb = sm + h * 64 * 60 + kt * 8;
            #pragma unroll
            for (int m = 0; m < 2; m++) {
                int r = (mh * 2 + m) * 16 + g;
                a[m][0] = Pb[r * 60 + tg];       a[m][1] = Pb[(r + 8) * 60 + tg];
                a[m][2] = Pb[r * 60 + tg + 4];   a[m][3] = Pb[(r + 8) * 60 + tg + 4];
            }
            const unsigned* Vb = sm + VOFF + h * 56 * 40;
            #pragma unroll
            for (int n = 0; n < 4; n++) {
                int nn = n * 8 + g;
                bb[n][0] = Vb[(kt * 8 + tg) * 40 + nn];
                bb[n][1] = Vb[(kt * 8 + tg + 4) * 40 + nn];
            }
            #pragma unroll
            for (int m = 0; m < 2; m++)
                #pragma unroll
                for (int n = 0; n < 4; n++) mma8(av[m][n], a[m], bb[n]);
        }
        #pragma unroll
        for (int m = 0; m < 2; m++)
            #pragma unroll
            for (int hc = 0; hc < 2; hc++) {
                int row = (mh * 2 + m) * 16 + g + hc * 8;
                if (row < 49) {
                    #pragma unroll
                    for (int n = 0; n < 4; n++) {
                        uint2 pv;
                        pv.x = f2tf(av[m][n][hc * 2]);
                        pv.y = f2tf(av[m][n][hc * 2 + 1]);
                        *(uint2*)&sm[XOFF + row * 132 + h * 32 + n * 8 + 2 * tg] = pv;
                    }
                }
            }
    }
    __syncthreads();

    // ================= Phase E: out = AO @ Wproj + b =================
    {
        float pc[4][2][4];
        #pragma unroll
        for (int mt = 0; mt < 4; mt++)
            #pragma unroll
            for (int n = 0; n < 2; n++)
                #pragma unroll
                for (int c = 0; c < 4; c++) pc[mt][n][c] = 0.f;

        const int colbase = warp * 16;
        unsigned bc[2][2];
        #pragma unroll
        for (int n = 0; n < 2; n++) {
            int col = colbase + n * 8 + g;
            bc[n][0] = g_wproj[tg * 128 + col];
            bc[n][1] = g_wproj[(tg + 4) * 128 + col];
        }
        #pragma unroll
        for (int kt = 0; kt < 16; kt++) {
            unsigned bn[2][2];
            if (kt < 15) {
                int k0 = (kt + 1) * 8;
                #pragma unroll
                for (int n = 0; n < 2; n++) {
                    int col = colbase + n * 8 + g;
                    bn[n][0] = g_wproj[(k0 + tg) * 128 + col];
                    bn[n][1] = g_wproj[(k0 + tg + 4) * 128 + col];
                }
            }
            unsigned a[4][4];
            const unsigned* X = sm + XOFF + kt * 8;
            #pragma unroll
            for (int mt = 0; mt < 4; mt++) {
                int r = mt * 16 + g;
                a[mt][0] = X[r * 132 + tg];       a[mt][1] = X[(r + 8) * 132 + tg];
                a[mt][2] = X[r * 132 + tg + 4];   a[mt][3] = X[(r + 8) * 132 + tg + 4];
            }
            #pragma unroll
            for (int mt = 0; mt < 4; mt++)
                #pragma unroll
                for (int n = 0; n < 2; n++) mma8(pc[mt][n], a[mt], bc[n]);
            if (kt < 15) {
                #pragma unroll
                for (int n = 0; n < 2; n++) { bc[n][0] = bn[n][0]; bc[n][1] = bn[n][1]; }
            }
        }
        float* ob = out + (size_t)b * 6272;
        #pragma unroll
        for (int mt = 0; mt < 4; mt++)
            #pragma unroll
            for (int hc = 0; hc < 2; hc++) {
                int row = mt * 16 + g + hc * 8;
                if (row < 49) {
                    #pragma unroll
                    for (int n = 0; n < 2; n++) {
                        int col = colbase + n * 8 + 2 * tg;
                        float2 v;
                        v.x = pc[mt][n][hc * 2]     + proj_b[col];
                        v.y = pc[mt][n][hc * 2 + 1] + proj_b[col + 1];
                        *(float2*)&ob[row * 128 + col] = v;
                    }
                }
            }
    }
}

extern "C" void kernel_launch(void* const* d_in, const int* in_sizes, int n_in,
                              void* d_out, int out_size)
{
    const float* x        = (const float*)d_in[0];
    const float* mask     = (const float*)d_in[1];
    const float* qkv_w    = (const float*)d_in[2];
    const float* qkv_b    = (const float*)d_in[3];
    const float* proj_w   = (const float*)d_in[4];
    const float* proj_b   = (const float*)d_in[5];
    const float* bias_tab = (const float*)d_in[6];
    float* out = (float*)d_out;

    cudaFuncSetAttribute(win_attn_mma,
                         cudaFuncAttributeMaxDynamicSharedMemorySize,
                         SMEM_WORDS * 4);

    prep_kernel<<<512, 256>>>(mask, bias_tab, qkv_w, proj_w);
    win_attn_mma<<<4096, 256, SMEM_WORDS * 4>>>(x, qkv_b, proj_b, out);
}

// round 4
// speedup vs baseline: 3.5882x; 1.4052x over previous
#include <cuda_runtime.h>

// smem word offsets (4-byte words). All matrices hold tf32 bit patterns.
// Region 1 (words 0..8447):   X [64][132]  ->  V^T [4][32][60] (after phase A)
// Region 2 (words 8448..25727): Q [4][64][36] + K [4][56][36]
//                               -> P [4][64][60]  -> AO [64][132]
#define XOFF  0
#define VTOFF 0
#define QOFF  8448
#define KOFF  (QOFF + 9216)     // 17664
#define POFF  8448
#define AOOFF 8448
#define SMEM_WORDS 25728        // 102912 bytes -> 2 CTAs/SM

__device__ unsigned g_wqkv[128 * 384];
__device__ unsigned g_wproj[128 * 128];
__device__ float    g_fused[64 * 4 * 49 * 56];  // mask + rel_bias

__device__ __forceinline__ unsigned f2tf(float f) {
    unsigned r; asm("cvt.rna.tf32.f32 %0, %1;" : "=r"(r) : "f"(f)); return r;
}
__device__ __forceinline__ void mma8(float* d, const unsigned* a, const unsigned* b) {
    asm volatile("mma.sync.aligned.m16n8k8.row.col.f32.tf32.tf32.f32 "
                 "{%0,%1,%2,%3},{%4,%5,%6,%7},{%8,%9},{%0,%1,%2,%3};"
                 : "+f"(d[0]), "+f"(d[1]), "+f"(d[2]), "+f"(d[3])
                 : "r"(a[0]), "r"(a[1]), "r"(a[2]), "r"(a[3]), "r"(b[0]), "r"(b[1]));
}

__global__ void prep_kernel(const float* __restrict__ mask,
                            const float* __restrict__ bias_tab,
                            const float* __restrict__ qkv_w,
                            const float* __restrict__ proj_w) {
    const int stride = gridDim.x * blockDim.x;
    const int t0 = blockIdx.x * blockDim.x + threadIdx.x;
    for (int i = t0; i < 128 * 384; i += stride) g_wqkv[i] = f2tf(qkv_w[i]);
    for (int i = t0; i < 128 * 128; i += stride) g_wproj[i] = f2tf(proj_w[i]);
    for (int e = t0; e < 64 * 4 * 49 * 49; e += stride) {
        int j = e % 49; int t = e / 49; int i = t % 49; t /= 49;
        int h = t & 3;  int w = t >> 2;
        int ih = i / 7, iw = i - ih * 7, jh = j / 7, jw = j - jh * 7;
        int ridx = (ih - jh + 6) * 13 + (iw - jw + 6);
        g_fused[((w * 4 + h) * 49 + i) * 56 + j] =
            mask[w * 2401 + i * 49 + j] + bias_tab[ridx * 4 + h];
    }
}

__global__ __launch_bounds__(256, 2)
void win_attn_mma(const float* __restrict__ x,
                  const float* __restrict__ qkv_b,
                  const float* __restrict__ proj_b,
                  float* __restrict__ out)
{
    extern __shared__ unsigned sm[];
    const int b = blockIdx.x, tid = threadIdx.x, lane = tid & 31, warp = tid >> 5;
    const int g = lane >> 2, tg = lane & 3;

    // ---- zero pads ----
    for (int i = tid; i < 1980; i += 256) sm[XOFF + 49 * 132 + i] = 0;                       // X rows 49..63
    for (int i = tid; i < 2160; i += 256) { int d = i % 36, t = i / 36, r = 49 + t % 15, h = t / 15; sm[QOFF + (h * 64 + r) * 36 + d] = 0; }
    for (int i = tid; i < 1008; i += 256) { int d = i % 36, t = i / 36, r = 49 + t % 7,  h = t / 7;  sm[KOFF + (h * 56 + r) * 36 + d] = 0; }
    // ---- load x -> X (tf32) ----
    const float* xg = x + (size_t)b * 6272;
    for (int i = tid; i < 6272; i += 256) { int r = i >> 7, c = i & 127; sm[XOFF + r * 132 + c] = f2tf(xg[i]); }
    __syncthreads();

    const int colq = warp * 16;                 // per-warp q/k/v column base (0..127 space)
    const float scale = 0.17677669529663687f;

    // ================= Phase A pass 1: Q,K = X @ Wqkv[:,q|k] =================
    {
        float acc[4][4][4];
        #pragma unroll
        for (int mt = 0; mt < 4; mt++)
            #pragma unroll
            for (int nt = 0; nt < 4; nt++)
                #pragma unroll
                for (int c = 0; c < 4; c++) acc[mt][nt][c] = 0.f;

        unsigned bc[4][2];
        #pragma unroll
        for (int nt = 0; nt < 4; nt++) {
            int col = (nt < 2 ? colq + nt * 8 : 128 + colq + (nt - 2) * 8) + g;
            bc[nt][0] = g_wqkv[tg * 384 + col];
            bc[nt][1] = g_wqkv[(tg + 4) * 384 + col];
        }
        #pragma unroll
        for (int kt = 0; kt < 16; kt++) {
            unsigned bn[4][2];
            if (kt < 15) {
                int k0 = (kt + 1) * 8;
                #pragma unroll
                for (int nt = 0; nt < 4; nt++) {
                    int col = (nt < 2 ? colq + nt * 8 : 128 + colq + (nt - 2) * 8) + g;
                    bn[nt][0] = g_wqkv[(k0 + tg) * 384 + col];
                    bn[nt][1] = g_wqkv[(k0 + tg + 4) * 384 + col];
                }
            }
            unsigned a[4][4];
            const unsigned* X = sm + XOFF + kt * 8;
            #pragma unroll
            for (int mt = 0; mt < 4; mt++) {
                int r = mt * 16 + g;
                a[mt][0] = X[r * 132 + tg];       a[mt][1] = X[(r + 8) * 132 + tg];
                a[mt][2] = X[r * 132 + tg + 4];   a[mt][3] = X[(r + 8) * 132 + tg + 4];
            }
            #pragma unroll
            for (int mt = 0; mt < 4; mt++)
                #pragma unroll
                for (int nt = 0; nt < 4; nt++) mma8(acc[mt][nt], a[mt], bc[nt]);
            if (kt < 15) {
                #pragma unroll
                for (int nt = 0; nt < 4; nt++) { bc[nt][0] = bn[nt][0]; bc[nt][1] = bn[nt][1]; }
            }
        }
        #pragma unroll
        for (int mt = 0; mt < 4; mt++)
            #pragma unroll
            for (int hc = 0; hc < 2; hc++) {
                int row = mt * 16 + g + hc * 8;
                if (row < 49) {
                    #pragma unroll
                    for (int nt = 0; nt < 2; nt++) {          // q
                        int G = colq + nt * 8 + 2 * tg;
                        float v0 = (acc[mt][nt][hc * 2]     + qkv_b[G])     * scale;
                        float v1 = (acc[mt][nt][hc * 2 + 1] + qkv_b[G + 1]) * scale;
                        uint2 pv; pv.x = f2tf(v0); pv.y = f2tf(v1);
                        *(uint2*)&sm[QOFF + ((G >> 5) * 64 + row) * 36 + (G & 31)] = pv;
                    }
                    #pragma unroll
                    for (int nt = 2; nt < 4; nt++) {          // k
                        int G = colq + (nt - 2) * 8 + 2 * tg;
                        float v0 = acc[mt][nt][hc * 2]     + qkv_b[128 + G];
                        float v1 = acc[mt][nt][hc * 2 + 1] + qkv_b[129 + G];
                        uint2 pv; pv.x = f2tf(v0); pv.y = f2tf(v1);
                        *(uint2*)&sm[KOFF + ((G >> 5) * 56 + row) * 36 + (G & 31)] = pv;
                    }
                }
            }
    }

    // ================= Phase A pass 2: V (held in regs, then -> V^T over X) =================
    {
        float vacc[4][2][4];
        #pragma unroll
        for (int mt = 0; mt < 4; mt++)
            #pragma unroll
            for (int nt = 0; nt < 2; nt++)
                #pragma unroll
                for (int c = 0; c < 4; c++) vacc[mt][nt][c] = 0.f;

        #pragma unroll
        for (int kt = 0; kt < 16; kt++) {
            unsigned bv[2][2];
            #pragma unroll
            for (int nt = 0; nt < 2; nt++) {
                int col = 256 + colq + nt * 8 + g;
                bv[nt][0] = g_wqkv[(kt * 8 + tg) * 384 + col];
                bv[nt][1] = g_wqkv[(kt * 8 + tg + 4) * 384 + col];
            }
            unsigned a[4][4];
            const unsigned* X = sm + XOFF + kt * 8;
            #pragma unroll
            for (int mt = 0; mt < 4; mt++) {
                int r = mt * 16 + g;
                a[mt][0] = X[r * 132 + tg];       a[mt][1] = X[(r + 8) * 132 + tg];
                a[mt][2] = X[r * 132 + tg + 4];   a[mt][3] = X[(r + 8) * 132 + tg + 4];
            }
            #pragma unroll
            for (int mt = 0; mt < 4; mt++)
                #pragma unroll
                for (int nt = 0; nt < 2; nt++) mma8(vacc[mt][nt], a[mt], bv[nt]);
        }
        __syncthreads();   // all X reads done; X region becomes V^T
        // zero V^T token-cols 49..59
        for (int i = tid; i < 128 * 11; i += 256) { int r = i / 11, c = 49 + i % 11; sm[VTOFF + r * 60 + c] = 0; }
        #pragma unroll
        for (int mt = 0; mt < 4; mt++)
            #pragma unroll
            for (int hc = 0; hc < 2; hc++) {
                int row = mt * 16 + g + hc * 8;
                if (row < 49) {
                    #pragma unroll
                    for (int nt = 0; nt < 2; nt++) {
                        int G = colq + nt * 8 + 2 * tg;       // 0..127
                        int h = G >> 5, d = G & 31;
                        sm[VTOFF + (h * 32 + d)     * 60 + row] = f2tf(vacc[mt][nt][hc * 2]     + qkv_b[256 + G]);
                        sm[VTOFF + (h * 32 + d + 1) * 60 + row] = f2tf(vacc[mt][nt][hc * 2 + 1] + qkv_b[257 + G]);
                    }
                }
            }
    }
    __syncthreads();

    // ================= Phase S: scores + softmax (in regs) =================
    const int h = warp >> 1, mh = warp & 1;
    float sacc[2][7][4];
    {
        #pragma unroll
        for (int m = 0; m < 2; m++)
            #pragma unroll
            for (int n = 0; n < 7; n++)
                #pragma unroll
                for (int c = 0; c < 4; c++) sacc[m][n][c] = 0.f;
        #pragma unroll
        for (int kt = 0; kt < 4; kt++) {
            unsigned a[2][4], bb[7][2];
            const unsigned* Qb = sm + QOFF + h * 64 * 36 + kt * 8;
            #pragma unroll
            for (int m = 0; m < 2; m++) {
                int r = (mh * 2 + m) * 16 + g;
                a[m][0] = Qb[r * 36 + tg];       a[m][1] = Qb[(r + 8) * 36 + tg];
                a[m][2] = Qb[r * 36 + tg + 4];   a[m][3] = Qb[(r + 8) * 36 + tg + 4];
            }
            const unsigned* Kb = sm + KOFF + h * 56 * 36 + kt * 8;
            #pragma unroll
            for (int n = 0; n < 7; n++) {
                int nn = n * 8 + g;
                bb[n][0] = Kb[nn * 36 + tg]; bb[n][1] = Kb[nn * 36 + tg + 4];
            }
            #pragma unroll
            for (int m = 0; m < 2; m++)
                #pragma unroll
                for (int n = 0; n < 7; n++) mma8(sacc[m][n], a[m], bb[n]);
        }
        const float* fus = g_fused + (((b & 63) * 4 + h) * 49) * 56;
        #pragma unroll
        for (int m = 0; m < 2; m++)
            #pragma unroll
            for (int hc = 0; hc < 2; hc++) {
                int row = (mh * 2 + m) * 16 + g + hc * 8;
                float vals[14]; float vmax = -1e30f;
                #pragma unroll
                for (int n = 0; n < 7; n++) {
                    int j = n * 8 + 2 * tg;
                    float f0 = 0.f, f1 = 0.f;
                    if (row < 49) {
                        float2 fv = *(const float2*)&fus[row * 56 + j];
                        f0 = fv.x; f1 = fv.y;
                    }
                    float v0 = (j < 49)     ? sacc[m][n][hc * 2]     + f0 : -1e30f;
                    float v1 = (j + 1 < 49) ? sacc[m][n][hc * 2 + 1] + f1 : -1e30f;
                    if (row >= 49) { v0 = (j < 49) ? 0.f : -1e30f; v1 = (j + 1 < 49) ? 0.f : -1e30f; }
                    vals[2 * n] = v0; vals[2 * n + 1] = v1;
                    vmax = fmaxf(vmax, fmaxf(v0, v1));
                }
                vmax = fmaxf(vmax, __shfl_xor_sync(0xffffffffu, vmax, 1));
                vmax = fmaxf(vmax, __shfl_xor_sync(0xffffffffu, vmax, 2));
                float s = 0.f;
                #pragma unroll
                for (int t = 0; t < 14; t++) { vals[t] = __expf(vals[t] - vmax); s += vals[t]; }
                s += __shfl_xor_sync(0xffffffffu, s, 1);
                s += __shfl_xor_sync(0xffffffffu, s, 2);
                float inv = 1.f / s;
                #pragma unroll
                for (int n = 0; n < 7; n++) {
                    sacc[m][n][hc * 2]     = vals[2 * n] * inv;
                    sacc[m][n][hc * 2 + 1] = vals[2 * n + 1] * inv;
                }
            }
    }
    __syncthreads();   // Q/K reads done before P overlays them
    {
        #pragma unroll
        for (int m = 0; m < 2; m++)
            #pragma unroll
            for (int hc = 0; hc < 2; hc++) {
                int row = (mh * 2 + m) * 16 + g + hc * 8;
                #pragma unroll
                for (int n = 0; n < 7; n++) {
                    uint2 pv;
                    pv.x = f2tf(sacc[m][n][hc * 2]);
                    pv.y = f2tf(sacc[m][n][hc * 2 + 1]);
                    *(uint2*)&sm[POFF + (h * 64 + row) * 60 + n * 8 + 2 * tg] = pv;
                }
            }
    }
    __syncthreads();

    // ================= Phase AV: AO = P @ V (V^T in region 1) =================
    {
        float av[2][4][4];
        #pragma unroll
        for (int m = 0; m < 2; m++)
            #pragma unroll
            for (int n = 0; n < 4; n++)
                #pragma unroll
                for (int c = 0; c < 4; c++) av[m][n][c] = 0.f;
        #pragma unroll
        for (int kt = 0; kt < 7; kt++) {
            unsigned a[2][4], bb[4][2];
            const unsigned* Pb = sm + POFF + h * 64 * 60 + kt * 8;
            #pragma unroll
            for (int m = 0; m < 2; m++) {
                int r = (mh * 2 + m) * 16 + g;
                a[m][0] = Pb[r * 60 + tg];       a[m][1] = Pb[(r + 8) * 60 + tg];
                a[m][2] = Pb[r * 60 + tg + 4];   a[m][3] = Pb[(r + 8) * 60 + tg + 4];
            }
            const unsigned* Vb = sm + VTOFF + h * 32 * 60;
            #pragma unroll
            for (int n = 0; n < 4; n++) {
                int nn = n * 8 + g;
                bb[n][0] = Vb[nn * 60 + kt * 8 + tg];
                bb[n][1] = Vb[nn * 60 + kt * 8 + tg + 4];
            }
            #pragma unroll
            for (int m = 0; m < 2; m++)
                #pragma unroll
                for (int n = 0; n < 4; n++) mma8(av[m][n], a[m], bb[n]);
        }
        __syncthreads();   // P / V^T reads done; region 2 becomes AO
        #pragma unroll
        for (int m = 0; m < 2; m++)
            #pragma unroll
            for (int hc = 0; hc < 2; hc++) {
                int row = (mh * 2 + m) * 16 + g + hc * 8;
                if (row < 49) {
                    #pragma unroll
                    for (int n = 0; n < 4; n++) {
                        uint2 pv;
                        pv.x = f2tf(av[m][n][hc * 2]);
                        pv.y = f2tf(av[m][n][hc * 2 + 1]);
                        *(uint2*)&sm[AOOFF + row * 132 + h * 32 + n * 8 + 2 * tg] = pv;
                    }
                }
            }
    }
    __syncthreads();

    // ================= Phase E: out = AO @ Wproj + b =================
    {
        float pc[4][2][4];
        #pragma unroll
        for (int mt = 0; mt < 4; mt++)
            #pragma unroll
            for (int n = 0; n < 2; n++)
                #pragma unroll
                for (int c = 0; c < 4; c++) pc[mt][n][c] = 0.f;

        const int colbase = warp * 16;
        unsigned bc[2][2];
        #pragma unroll
        for (int n = 0; n < 2; n++) {
            int col = colbase + n * 8 + g;
            bc[n][0] = g_wproj[tg * 128 + col];
            bc[n][1] = g_wproj[(tg + 4) * 128 + col];
        }
        #pragma unroll
        for (int kt = 0; kt < 16; kt++) {
            unsigned bn[2][2];
            if (kt < 15) {
                int k0 = (kt + 1) * 8;
                #pragma unroll
                for (int n = 0; n < 2; n++) {
                    int col = colbase + n * 8 + g;
                    bn[n][0] = g_wproj[(k0 + tg) * 128 + col];
                    bn[n][1] = g_wproj[(k0 + tg + 4) * 128 + col];
                }
            }
            unsigned a[4][4];
            const unsigned* X = sm + AOOFF + kt * 8;
            #pragma unroll
            for (int mt = 0; mt < 4; mt++) {
                int r = mt * 16 + g;
                a[mt][0] = X[r * 132 + tg];       a[mt][1] = X[(r + 8) * 132 + tg];
                a[mt][2] = X[r * 132 + tg + 4];   a[mt][3] = X[(r + 8) * 132 + tg + 4];
            }
            #pragma unroll
            for (int mt = 0; mt < 4; mt++)
                #pragma unroll
                for (int n = 0; n < 2; n++) mma8(pc[mt][n], a[mt], bc[n]);
            if (kt < 15) {
                #pragma unroll
                for (int n = 0; n < 2; n++) { bc[n][0] = bn[n][0]; bc[n][1] = bn[n][1]; }
            }
        }
        float* ob = out + (size_t)b * 6272;
        #pragma unroll
        for (int mt = 0; mt < 4; mt++)
            #pragma unroll
            for (int hc = 0; hc < 2; hc++) {
                int row = mt * 16 + g + hc * 8;
                if (row < 49) {
                    #pragma unroll
                    for (int n = 0; n < 2; n++) {
                        int col = colbase + n * 8 + 2 * tg;
                        float2 v;
                        v.x = pc[mt][n][hc * 2]     + proj_b[col];
                        v.y = pc[mt][n][hc * 2 + 1] + proj_b[col + 1];
                        *(float2*)&ob[row * 128 + col] = v;
                    }
                }
            }
    }
}

extern "C" void kernel_launch(void* const* d_in, const int* in_sizes, int n_in,
                              void* d_out, int out_size)
{
    const float* x        = (const float*)d_in[0];
    const float* mask     = (const float*)d_in[1];
    const float* qkv_w    = (const float*)d_in[2];
    const float* qkv_b    = (const float*)d_in[3];
    const float* proj_w   = (const float*)d_in[4];
    const float* proj_b   = (const float*)d_in[5];
    const float* bias_tab = (const float*)d_in[6];
    float* out = (float*)d_out;

    cudaFuncSetAttribute(win_attn_mma,
                         cudaFuncAttributeMaxDynamicSharedMemorySize,
                         SMEM_WORDS * 4);

    prep_kernel<<<512, 256>>>(mask, bias_tab, qkv_w, proj_w);
    win_attn_mma<<<4096, 256, SMEM_WORDS * 4>>>(x, qkv_b, proj_b, out);
}

// round 5
// speedup vs baseline: 4.3372x; 1.2088x over previous
#include <cuda_runtime.h>
#include <cuda_fp16.h>

// smem word offsets (4-byte words = half2 pairs).
// Region 1 (0..4607):      X [64][68]  ->  V^T [4][32][36] (after phase A)
// Region 2 (4608..14207):  Q [4][64][20] + K [4][56][20]
//                          -> P [4][64][36] -> AO [64][68]
#define XOFF  0
#define VTOFF 0
#define QOFF  4608
#define KOFF  (QOFF + 5120)    // 9728
#define POFF  4608
#define AOOFF 4608
#define SMEM_WORDS 14208       // 56832 bytes -> 2 CTAs/SM (reg-limited)

__device__ unsigned g_wqkvT[384 * 64];   // W^T[n][kw] as half2 (k even = low half)
__device__ unsigned g_wprojT[128 * 64];
__device__ float    g_fused[64 * 4 * 49 * 56];  // mask + rel_bias

__device__ __forceinline__ unsigned f2h2(float a, float b) {
    __half2 h = __floats2half2_rn(a, b);
    return *(unsigned*)&h;
}
__device__ __forceinline__ void mma16(float* d, const unsigned* a, const unsigned* b) {
    asm volatile("mma.sync.aligned.m16n8k16.row.col.f32.f16.f16.f32 "
                 "{%0,%1,%2,%3},{%4,%5,%6,%7},{%8,%9},{%0,%1,%2,%3};"
                 : "+f"(d[0]), "+f"(d[1]), "+f"(d[2]), "+f"(d[3])
                 : "r"(a[0]), "r"(a[1]), "r"(a[2]), "r"(a[3]), "r"(b[0]), "r"(b[1]));
}

__global__ void prep_kernel(const float* __restrict__ mask,
                            const float* __restrict__ bias_tab,
                            const float* __restrict__ qkv_w,
                            const float* __restrict__ proj_w) {
    const int stride = gridDim.x * blockDim.x;
    const int t0 = blockIdx.x * blockDim.x + threadIdx.x;
    for (int i = t0; i < 384 * 64; i += stride) {
        int n = i >> 6, kw = i & 63;
        g_wqkvT[i] = f2h2(qkv_w[(2 * kw) * 384 + n], qkv_w[(2 * kw + 1) * 384 + n]);
    }
    for (int i = t0; i < 128 * 64; i += stride) {
        int n = i >> 6, kw = i & 63;
        g_wprojT[i] = f2h2(proj_w[(2 * kw) * 128 + n], proj_w[(2 * kw + 1) * 128 + n]);
    }
    for (int e = t0; e < 64 * 4 * 49 * 49; e += stride) {
        int j = e % 49; int t = e / 49; int i = t % 49; t /= 49;
        int h = t & 3;  int w = t >> 2;
        int ih = i / 7, iw = i - ih * 7, jh = j / 7, jw = j - jh * 7;
        int ridx = (ih - jh + 6) * 13 + (iw - jw + 6);
        g_fused[((w * 4 + h) * 49 + i) * 56 + j] =
            mask[w * 2401 + i * 49 + j] + bias_tab[ridx * 4 + h];
    }
}

__global__ __launch_bounds__(256, 2)
void win_attn_mma(const float* __restrict__ x,
                  const float* __restrict__ qkv_b,
                  const float* __restrict__ proj_b,
                  float* __restrict__ out)
{
    extern __shared__ unsigned sm[];
    const int b = blockIdx.x, tid = threadIdx.x, lane = tid & 31, warp = tid >> 5;
    const int g = lane >> 2, tg = lane & 3;

    // ---- zero pads ----
    for (int i = tid; i < 1020; i += 256) sm[XOFF + 49 * 68 + i] = 0;                        // X rows 49..63
    for (int i = tid; i < 1200; i += 256) { int d = i % 20, t = i / 20, r = 49 + t % 15, h = t / 15; sm[QOFF + (h * 64 + r) * 20 + d] = 0; }
    for (int i = tid; i < 560;  i += 256) { int d = i % 20, t = i / 20, r = 49 + t % 7,  h = t / 7;  sm[KOFF + (h * 56 + r) * 20 + d] = 0; }
    // ---- load x -> X (half2) ----
    const float* xg = x + (size_t)b * 6272;
    for (int i = tid; i < 3136; i += 256) {
        int r = i >> 6, cw = i & 63;
        float2 xv = *(const float2*)(xg + r * 128 + 2 * cw);
        sm[XOFF + r * 68 + cw] = f2h2(xv.x, xv.y);
    }
    __syncthreads();

    const int colq = warp * 16;
    const float scale = 0.17677669529663687f;

    // ================= Phase A pass 1: Q,K = X @ Wqkv[:,q|k] =================
    {
        float acc[4][4][4];
        #pragma unroll
        for (int mt = 0; mt < 4; mt++)
            #pragma unroll
            for (int nt = 0; nt < 4; nt++)
                #pragma unroll
                for (int c = 0; c < 4; c++) acc[mt][nt][c] = 0.f;

        unsigned bc[4][2];
        #pragma unroll
        for (int nt = 0; nt < 4; nt++) {
            int col = (nt < 2 ? colq + nt * 8 : 128 + colq + (nt - 2) * 8) + g;
            bc[nt][0] = g_wqkvT[col * 64 + tg];
            bc[nt][1] = g_wqkvT[col * 64 + tg + 4];
        }
        #pragma unroll
        for (int kt = 0; kt < 8; kt++) {
            unsigned bn[4][2];
            if (kt < 7) {
                int k0 = (kt + 1) * 8;
                #pragma unroll
                for (int nt = 0; nt < 4; nt++) {
                    int col = (nt < 2 ? colq + nt * 8 : 128 + colq + (nt - 2) * 8) + g;
                    bn[nt][0] = g_wqkvT[col * 64 + k0 + tg];
                    bn[nt][1] = g_wqkvT[col * 64 + k0 + tg + 4];
                }
            }
            unsigned a[4][4];
            const unsigned* X = sm + XOFF + kt * 8;
            #pragma unroll
            for (int mt = 0; mt < 4; mt++) {
                int r = mt * 16 + g;
                a[mt][0] = X[r * 68 + tg];       a[mt][1] = X[(r + 8) * 68 + tg];
                a[mt][2] = X[r * 68 + tg + 4];   a[mt][3] = X[(r + 8) * 68 + tg + 4];
            }
            #pragma unroll
            for (int mt = 0; mt < 4; mt++)
                #pragma unroll
                for (int nt = 0; nt < 4; nt++) mma16(acc[mt][nt], a[mt], bc[nt]);
            if (kt < 7) {
                #pragma unroll
                for (int nt = 0; nt < 4; nt++) { bc[nt][0] = bn[nt][0]; bc[nt][1] = bn[nt][1]; }
            }
        }
        #pragma unroll
        for (int mt = 0; mt < 4; mt++)
            #pragma unroll
            for (int hc = 0; hc < 2; hc++) {
                int row = mt * 16 + g + hc * 8;
                if (row < 49) {
                    #pragma unroll
                    for (int nt = 0; nt < 2; nt++) {          // q
                        int G = colq + nt * 8 + 2 * tg;
                        float v0 = (acc[mt][nt][hc * 2]     + qkv_b[G])     * scale;
                        float v1 = (acc[mt][nt][hc * 2 + 1] + qkv_b[G + 1]) * scale;
                        sm[QOFF + ((G >> 5) * 64 + row) * 20 + ((G & 31) >> 1)] = f2h2(v0, v1);
                    }
                    #pragma unroll
                    for (int nt = 2; nt < 4; nt++) {          // k
                        int G = colq + (nt - 2) * 8 + 2 * tg;
                        float v0 = acc[mt][nt][hc * 2]     + qkv_b[128 + G];
                        float v1 = acc[mt][nt][hc * 2 + 1] + qkv_b[129 + G];
                        sm[KOFF + ((G >> 5) * 56 + row) * 20 + ((G & 31) >> 1)] = f2h2(v0, v1);
                    }
                }
            }
    }

    // ================= Phase A pass 2: V (regs) -> V^T over X =================
    {
        float vacc[4][2][4];
        #pragma unroll
        for (int mt = 0; mt < 4; mt++)
            #pragma unroll
            for (int nt = 0; nt < 2; nt++)
                #pragma unroll
                for (int c = 0; c < 4; c++) vacc[mt][nt][c] = 0.f;

        #pragma unroll
        for (int kt = 0; kt < 8; kt++) {
            unsigned bv[2][2];
            #pragma unroll
            for (int nt = 0; nt < 2; nt++) {
                int col = 256 + colq + nt * 8 + g;
                bv[nt][0] = g_wqkvT[col * 64 + kt * 8 + tg];
                bv[nt][1] = g_wqkvT[col * 64 + kt * 8 + tg + 4];
            }
            unsigned a[4][4];
            const unsigned* X = sm + XOFF + kt * 8;
            #pragma unroll
            for (int mt = 0; mt < 4; mt++) {
                int r = mt * 16 + g;
                a[mt][0] = X[r * 68 + tg];       a[mt][1] = X[(r + 8) * 68 + tg];
                a[mt][2] = X[r * 68 + tg + 4];   a[mt][3] = X[(r + 8) * 68 + tg + 4];
            }
            #pragma unroll
            for (int mt = 0; mt < 4; mt++)
                #pragma unroll
                for (int nt = 0; nt < 2; nt++) mma16(vacc[mt][nt], a[mt], bv[nt]);
        }
        __syncthreads();   // X reads done; region 1 becomes V^T
        // zero V^T halves for tokens 49..63 (halves 49..63 of each d-row; never re-written)
        {
            __half* vt = (__half*)(sm + VTOFF);
            for (int i = tid; i < 128 * 15; i += 256) {
                int dr = i / 15, t = 49 + i % 15;
                vt[dr * 72 + t] = __float2half(0.f);
            }
        }
        __half* vt = (__half*)(sm + VTOFF);
        #pragma unroll
        for (int mt = 0; mt < 4; mt++)
            #pragma unroll
            for (int hc = 0; hc < 2; hc++) {
                int row = mt * 16 + g + hc * 8;
                if (row < 49) {
                    #pragma unroll
                    for (int nt = 0; nt < 2; nt++) {
                        int G = colq + nt * 8 + 2 * tg;       // 0..127
                        int h = G >> 5, d = G & 31;
                        vt[(h * 32 + d)     * 72 + row] = __float2half(vacc[mt][nt][hc * 2]     + qkv_b[256 + G]);
                        vt[(h * 32 + d + 1) * 72 + row] = __float2half(vacc[mt][nt][hc * 2 + 1] + qkv_b[257 + G]);
                    }
                }
            }
    }
    __syncthreads();

    // ================= Phase S: scores + softmax (in regs) =================
    const int h = warp >> 1, mh = warp & 1;
    float sacc[2][7][4];
    {
        #pragma unroll
        for (int m = 0; m < 2; m++)
            #pragma unroll
            for (int n = 0; n < 7; n++)
                #pragma unroll
                for (int c = 0; c < 4; c++) sacc[m][n][c] = 0.f;
        #pragma unroll
        for (int kt = 0; kt < 2; kt++) {
            unsigned a[2][4], bb[7][2];
            const unsigned* Qb = sm + QOFF + h * 64 * 20 + kt * 8;
            #pragma unroll
            for (int m = 0; m < 2; m++) {
                int r = (mh * 2 + m) * 16 + g;
                a[m][0] = Qb[r * 20 + tg];       a[m][1] = Qb[(r + 8) * 20 + tg];
                a[m][2] = Qb[r * 20 + tg + 4];   a[m][3] = Qb[(r + 8) * 20 + tg + 4];
            }
            const unsigned* Kb = sm + KOFF + h * 56 * 20 + kt * 8;
            #pragma unroll
            for (int n = 0; n < 7; n++) {
                int nn = n * 8 + g;
                bb[n][0] = Kb[nn * 20 + tg]; bb[n][1] = Kb[nn * 20 + tg + 4];
            }
            #pragma unroll
            for (int m = 0; m < 2; m++)
                #pragma unroll
                for (int n = 0; n < 7; n++) mma16(sacc[m][n], a[m], bb[n]);
        }
        const float* fus = g_fused + (((b & 63) * 4 + h) * 49) * 56;
        #pragma unroll
        for (int m = 0; m < 2; m++)
            #pragma unroll
            for (int hc = 0; hc < 2; hc++) {
                int row = (mh * 2 + m) * 16 + g + hc * 8;
                float vals[14]; float vmax = -1e30f;
                #pragma unroll
                for (int n = 0; n < 7; n++) {
                    int j = n * 8 + 2 * tg;
                    float f0 = 0.f, f1 = 0.f;
                    if (row < 49) {
                        float2 fv = *(const float2*)&fus[row * 56 + j];
                        f0 = fv.x; f1 = fv.y;
                    }
                    float v0 = (j < 49)     ? sacc[m][n][hc * 2]     + f0 : -1e30f;
                    float v1 = (j + 1 < 49) ? sacc[m][n][hc * 2 + 1] + f1 : -1e30f;
                    if (row >= 49) { v0 = (j < 49) ? 0.f : -1e30f; v1 = (j + 1 < 49) ? 0.f : -1e30f; }
                    vals[2 * n] = v0; vals[2 * n + 1] = v1;
                    vmax = fmaxf(vmax, fmaxf(v0, v1));
                }
                vmax = fmaxf(vmax, __shfl_xor_sync(0xffffffffu, vmax, 1));
                vmax = fmaxf(vmax, __shfl_xor_sync(0xffffffffu, vmax, 2));
                float s = 0.f;
                #pragma unroll
                for (int t = 0; t < 14; t++) { vals[t] = __expf(vals[t] - vmax); s += vals[t]; }
                s += __shfl_xor_sync(0xffffffffu, s, 1);
                s += __shfl_xor_sync(0xffffffffu, s, 2);
                float inv = 1.f / s;
                #pragma unroll
                for (int n = 0; n < 7; n++) {
                    sacc[m][n][hc * 2]     = vals[2 * n] * inv;
                    sacc[m][n][hc * 2 + 1] = vals[2 * n + 1] * inv;
                }
            }
    }
    __syncthreads();   // Q/K reads done before P overlays them
    {
        // zero P pad words (tokens 56..63) for all rows
        for (int i = tid; i < 1024; i += 256) {
            int rr = i >> 2, w = 28 + (i & 3);
            sm[POFF + rr * 36 + w] = 0;
        }
        #pragma unroll
        for (int m = 0; m < 2; m++)
            #pragma unroll
            for (int hc = 0; hc < 2; hc++) {
                int row = (mh * 2 + m) * 16 + g + hc * 8;
                #pragma unroll
                for (int n = 0; n < 7; n++) {
                    sm[POFF + (h * 64 + row) * 36 + n * 4 + tg] =
                        f2h2(sacc[m][n][hc * 2], sacc[m][n][hc * 2 + 1]);
                }
            }
    }
    __syncthreads();

    // ================= Phase AV: AO = P @ V (V^T in region 1) =================
    {
        float av[2][4][4];
        #pragma unroll
        for (int m = 0; m < 2; m++)
            #pragma unroll
            for (int n = 0; n < 4; n++)
                #pragma unroll
                for (int c = 0; c < 4; c++) av[m][n][c] = 0.f;
        #pragma unroll
        for (int kt = 0; kt < 4; kt++) {
            unsigned a[2][4], bb[4][2];
            const unsigned* Pb = sm + POFF + h * 64 * 36 + kt * 8;
            #pragma unroll
            for (int m = 0; m < 2; m++) {
                int r = (mh * 2 + m) * 16 + g;
                a[m][0] = Pb[r * 36 + tg];       a[m][1] = Pb[(r + 8) * 36 + tg];
                a[m][2] = Pb[r * 36 + tg + 4];   a[m][3] = Pb[(r + 8) * 36 + tg + 4];
            }
            const unsigned* Vb = sm + VTOFF + h * 32 * 36 + kt * 8;
            #pragma unroll
            for (int n = 0; n < 4; n++) {
                int nn = n * 8 + g;
                bb[n][0] = Vb[nn * 36 + tg];
                bb[n][1] = Vb[nn * 36 + tg + 4];
            }
            #pragma unroll
            for (int m = 0; m < 2; m++)
                #pragma unroll
                for (int n = 0; n < 4; n++) mma16(av[m][n], a[m], bb[n]);
        }
        __syncthreads();   // P / V^T reads done; region 2 becomes AO
        #pragma unroll
        for (int m = 0; m < 2; m++)
            #pragma unroll
            for (int hc = 0; hc < 2; hc++) {
                int row = (mh * 2 + m) * 16 + g + hc * 8;
                if (row < 49) {
                    #pragma unroll
                    for (int n = 0; n < 4; n++) {
                        sm[AOOFF + row * 68 + h * 16 + n * 4 + tg] =
                            f2h2(av[m][n][hc * 2], av[m][n][hc * 2 + 1]);
                    }
                }
            }
    }
    __syncthreads();

    // ================= Phase E: out = AO @ Wproj + b =================
    {
        float pc[4][2][4];
        #pragma unroll
        for (int mt = 0; mt < 4; mt++)
            #pragma unroll
            for (int n = 0; n < 2; n++)
                #pragma unroll
                for (int c = 0; c < 4; c++) pc[mt][n][c] = 0.f;

        const int colbase = warp * 16;
        unsigned bc[2][2];
        #pragma unroll
        for (int n = 0; n < 2; n++) {
            int col = colbase + n * 8 + g;
            bc[n][0] = g_wprojT[col * 64 + tg];
            bc[n][1] = g_wprojT[col * 64 + tg + 4];
        }
        #pragma unroll
        for (int kt = 0; kt < 8; kt++) {
            unsigned bn[2][2];
            if (kt < 7) {
                int k0 = (kt + 1) * 8;
                #pragma unroll
                for (int n = 0; n < 2; n++) {
                    int col = colbase + n * 8 + g;
                    bn[n][0] = g_wprojT[col * 64 + k0 + tg];
                    bn[n][1] = g_wprojT[col * 64 + k0 + tg + 4];
                }
            }
            unsigned a[4][4];
            const unsigned* X = sm + AOOFF + kt * 8;
            #pragma unroll
            for (int mt = 0; mt < 4; mt++) {
                int r = mt * 16 + g;
                a[mt][0] = X[r * 68 + tg];       a[mt][1] = X[(r + 8) * 68 + tg];
                a[mt][2] = X[r * 68 + tg + 4];   a[mt][3] = X[(r + 8) * 68 + tg + 4];
            }
            #pragma unroll
            for (int mt = 0; mt < 4; mt++)
                #pragma unroll
                for (int n = 0; n < 2; n++) mma16(pc[mt][n], a[mt], bc[n]);
            if (kt < 7) {
                #pragma unroll
                for (int n = 0; n < 2; n++) { bc[n][0] = bn[n][0]; bc[n][1] = bn[n][1]; }
            }
        }
        float* ob = out + (size_t)b * 6272;
        #pragma unroll
        for (int mt = 0; mt < 4; mt++)
            #pragma unroll
            for (int hc = 0; hc < 2; hc++) {
                int row = mt * 16 + g + hc * 8;
                if (row < 49) {
                    #pragma unroll
                    for (int n = 0; n < 2; n++) {
                        int col = colbase + n * 8 + 2 * tg;
                        float2 v;
                        v.x = pc[mt][n][hc * 2]     + proj_b[col];
                        v.y = pc[mt][n][hc * 2 + 1] + proj_b[col + 1];
                        *(float2*)&ob[row * 128 + col] = v;
                    }
                }
            }
    }
}

extern "C" void kernel_launch(void* const* d_in, const int* in_sizes, int n_in,
                              void* d_out, int out_size)
{
    const float* x        = (const float*)d_in[0];
    const float* mask     = (const float*)d_in[1];
    const float* qkv_w    = (const float*)d_in[2];
    const float* qkv_b    = (const float*)d_in[3];
    const float* proj_w   = (const float*)d_in[4];
    const float* proj_b   = (const float*)d_in[5];
    const float* bias_tab = (const float*)d_in[6];
    float* out = (float*)d_out;

    cudaFuncSetAttribute(win_attn_mma,
                         cudaFuncAttributeMaxDynamicSharedMemorySize,
                         SMEM_WORDS * 4);

    prep_kernel<<<512, 256>>>(mask, bias_tab, qkv_w, proj_w);
    win_attn_mma<<<4096, 256, SMEM_WORDS * 4>>>(x, qkv_b, proj_b, out);
}

// round 7
// speedup vs baseline: 4.4671x; 1.0299x over previous
#include <cuda_runtime.h>
#include <cuda_fp16.h>

// smem word offsets (4-byte words = half2 pairs).
// Region 1 (0..4607):      X [64][68]  ->  V^T [4][32][36] (after phase A)
// Region 2 (4608..14207):  Q [4][64][20] + K [4][56][20]
//                          -> P [4][64][36] -> AO [64][68]
#define XOFF  0
#define VTOFF 0
#define QOFF  4608
#define KOFF  (QOFF + 5120)    // 9728
#define POFF  4608
#define AOOFF 4608
#define SMEM_WORDS 14208       // 56832 bytes -> 3 CTAs/SM (reg-limited)

__device__ unsigned g_wqkvT[384 * 64];   // W^T[n][kw] as half2
__device__ unsigned g_wprojT[128 * 64];
__device__ float    g_fused[64 * 4 * 49 * 56];  // mask + rel_bias

__device__ __forceinline__ unsigned f2h2(float a, float b) {
    __half2 h = __floats2half2_rn(a, b);
    return *(unsigned*)&h;
}
__device__ __forceinline__ void mma16(float* d, const unsigned* a, const unsigned* b) {
    asm volatile("mma.sync.aligned.m16n8k16.row.col.f32.f16.f16.f32 "
                 "{%0,%1,%2,%3},{%4,%5,%6,%7},{%8,%9},{%0,%1,%2,%3};"
                 : "+f"(d[0]), "+f"(d[1]), "+f"(d[2]), "+f"(d[3])
                 : "r"(a[0]), "r"(a[1]), "r"(a[2]), "r"(a[3]), "r"(b[0]), "r"(b[1]));
}
__device__ __forceinline__ void ldm4(unsigned* r, unsigned addr) {
    asm volatile("ldmatrix.sync.aligned.m8n8.x4.shared.b16 {%0,%1,%2,%3}, [%4];"
                 : "=r"(r[0]), "=r"(r[1]), "=r"(r[2]), "=r"(r[3]) : "r"(addr));
}
__device__ __forceinline__ void ldm2(unsigned* r, unsigned addr) {
    asm volatile("ldmatrix.sync.aligned.m8n8.x2.shared.b16 {%0,%1}, [%2];"
                 : "=r"(r[0]), "=r"(r[1]) : "r"(addr));
}

__global__ void prep_kernel(const float* __restrict__ mask,
                            const float* __restrict__ bias_tab,
                            const float* __restrict__ qkv_w,
                            const float* __restrict__ proj_w) {
    const int stride = gridDim.x * blockDim.x;
    const int t0 = blockIdx.x * blockDim.x + threadIdx.x;
    for (int i = t0; i < 384 * 64; i += stride) {
        int n = i >> 6, kw = i & 63;
        g_wqkvT[i] = f2h2(qkv_w[(2 * kw) * 384 + n], qkv_w[(2 * kw + 1) * 384 + n]);
    }
    for (int i = t0; i < 128 * 64; i += stride) {
        int n = i >> 6, kw = i & 63;
        g_wprojT[i] = f2h2(proj_w[(2 * kw) * 128 + n], proj_w[(2 * kw + 1) * 128 + n]);
    }
    for (int e = t0; e < 64 * 4 * 49 * 49; e += stride) {
        int j = e % 49; int t = e / 49; int i = t % 49; t /= 49;
        int h = t & 3;  int w = t >> 2;
        int ih = i / 7, iw = i - ih * 7, jh = j / 7, jw = j - jh * 7;
        int ridx = (ih - jh + 6) * 13 + (iw - jw + 6);
        g_fused[((w * 4 + h) * 49 + i) * 56 + j] =
            mask[w * 2401 + i * 49 + j] + bias_tab[ridx * 4 + h];
    }
}

__global__ __launch_bounds__(256, 3)
void win_attn_mma(const float* __restrict__ x,
                  const float* __restrict__ qkv_b,
                  const float* __restrict__ proj_b,
                  float* __restrict__ out)
{
    extern __shared__ unsigned sm[];
    const int b = blockIdx.x, tid = threadIdx.x, lane = tid & 31, warp = tid >> 5;
    const int g = lane >> 2, tg = lane & 3;
    // ldmatrix lane constants
    const int lrow = (lane & 7) + ((lane >> 3) & 1) * 8;   // A x4: row within 16
    const int kwo  = (lane >> 4) * 4;                      // A x4: k-word offset
    const int brow = lane & 7;                             // B x2: n-row
    const int bkwo = ((lane >> 3) & 1) * 4;                // B x2: k-word offset

    // ---- zero pads ----
    for (int i = tid; i < 1020; i += 256) sm[XOFF + 49 * 68 + i] = 0;
    for (int i = tid; i < 1200; i += 256) { int d = i % 20, t = i / 20, r = 49 + t % 15, h = t / 15; sm[QOFF + (h * 64 + r) * 20 + d] = 0; }
    for (int i = tid; i < 560;  i += 256) { int d = i % 20, t = i / 20, r = 49 + t % 7,  h = t / 7;  sm[KOFF + (h * 56 + r) * 20 + d] = 0; }
    // ---- load x -> X (half2) ----
    const float* xg = x + (size_t)b * 6272;
    for (int i = tid; i < 3136; i += 256) {
        int r = i >> 6, cw = i & 63;
        float2 xv = *(const float2*)(xg + r * 128 + 2 * cw);
        sm[XOFF + r * 68 + cw] = f2h2(xv.x, xv.y);
    }
    __syncthreads();

    const unsigned smu = (unsigned)__cvta_generic_to_shared(sm);
    const int colq = warp * 16;
    const float scale = 0.17677669529663687f;

    // ================= Phase A passes: 0 -> Q, 1 -> K =================
    #pragma unroll 1
    for (int pass = 0; pass < 2; pass++) {
        float acc[4][2][4];
        #pragma unroll
        for (int mt = 0; mt < 4; mt++)
            #pragma unroll
            for (int nt = 0; nt < 2; nt++)
                #pragma unroll
                for (int c = 0; c < 4; c++) acc[mt][nt][c] = 0.f;

        const int cb = pass * 128 + colq;
        unsigned bc[2][2];
        #pragma unroll
        for (int nt = 0; nt < 2; nt++) {
            int col = cb + nt * 8 + g;
            bc[nt][0] = g_wqkvT[col * 64 + tg];
            bc[nt][1] = g_wqkvT[col * 64 + tg + 4];
        }
        #pragma unroll
        for (int kt = 0; kt < 8; kt++) {
            unsigned bn[2][2];
            if (kt < 7) {
                int k0 = (kt + 1) * 8;
                #pragma unroll
                for (int nt = 0; nt < 2; nt++) {
                    int col = cb + nt * 8 + g;
                    bn[nt][0] = g_wqkvT[col * 64 + k0 + tg];
                    bn[nt][1] = g_wqkvT[col * 64 + k0 + tg + 4];
                }
            }
            unsigned a[4][4];
            #pragma unroll
            for (int mt = 0; mt < 4; mt++)
                ldm4(a[mt], smu + 4u * (XOFF + (mt * 16 + lrow) * 68 + kt * 8 + kwo));
            #pragma unroll
            for (int mt = 0; mt < 4; mt++)
                #pragma unroll
                for (int nt = 0; nt < 2; nt++) mma16(acc[mt][nt], a[mt], bc[nt]);
            if (kt < 7) {
                #pragma unroll
                for (int nt = 0; nt < 2; nt++) { bc[nt][0] = bn[nt][0]; bc[nt][1] = bn[nt][1]; }
            }
        }
        #pragma unroll
        for (int mt = 0; mt < 4; mt++)
            #pragma unroll
            for (int hc = 0; hc < 2; hc++) {
                int row = mt * 16 + g + hc * 8;
                if (row < 49) {
                    #pragma unroll
                    for (int nt = 0; nt < 2; nt++) {
                        int G = colq + nt * 8 + 2 * tg;     // 0..127
                        if (pass == 0) {
                            float v0 = (acc[mt][nt][hc * 2]     + qkv_b[G])     * scale;
                            float v1 = (acc[mt][nt][hc * 2 + 1] + qkv_b[G + 1]) * scale;
                            sm[QOFF + ((G >> 5) * 64 + row) * 20 + ((G & 31) >> 1)] = f2h2(v0, v1);
                        } else {
                            float v0 = acc[mt][nt][hc * 2]     + qkv_b[128 + G];
                            float v1 = acc[mt][nt][hc * 2 + 1] + qkv_b[129 + G];
                            sm[KOFF + ((G >> 5) * 56 + row) * 20 + ((G & 31) >> 1)] = f2h2(v0, v1);
                        }
                    }
                }
            }
    }

    // ================= Phase A pass 3: V (regs) -> V^T over X =================
    {
        float vacc[4][2][4];
        #pragma unroll
        for (int mt = 0; mt < 4; mt++)
            #pragma unroll
            for (int nt = 0; nt < 2; nt++)
                #pragma unroll
                for (int c = 0; c < 4; c++) vacc[mt][nt][c] = 0.f;

        #pragma unroll
        for (int kt = 0; kt < 8; kt++) {
            unsigned bv[2][2];
            #pragma unroll
            for (int nt = 0; nt < 2; nt++) {
                int col = 256 + colq + nt * 8 + g;
                bv[nt][0] = g_wqkvT[col * 64 + kt * 8 + tg];
                bv[nt][1] = g_wqkvT[col * 64 + kt * 8 + tg + 4];
            }
            unsigned a[4][4];
            #pragma unroll
            for (int mt = 0; mt < 4; mt++)
                ldm4(a[mt], smu + 4u * (XOFF + (mt * 16 + lrow) * 68 + kt * 8 + kwo));
            #pragma unroll
            for (int mt = 0; mt < 4; mt++)
                #pragma unroll
                for (int nt = 0; nt < 2; nt++) mma16(vacc[mt][nt], a[mt], bv[nt]);
        }
        __syncthreads();   // X reads done; region 1 becomes V^T
        {
            __half* vt = (__half*)(sm + VTOFF);
            for (int i = tid; i < 128 * 15; i += 256) {
                int dr = i / 15, t = 49 + i % 15;
                vt[dr * 72 + t] = __float2half(0.f);
            }
        }
        __half* vt = (__half*)(sm + VTOFF);
        #pragma unroll
        for (int mt = 0; mt < 4; mt++)
            #pragma unroll
            for (int hc = 0; hc < 2; hc++) {
                int row = mt * 16 + g + hc * 8;
                if (row < 49) {
                    #pragma unroll
                    for (int nt = 0; nt < 2; nt++) {
                        int G = colq + nt * 8 + 2 * tg;
                        int h = G >> 5, d = G & 31;
                        vt[(h * 32 + d)     * 72 + row] = __float2half(vacc[mt][nt][hc * 2]     + qkv_b[256 + G]);
                        vt[(h * 32 + d + 1) * 72 + row] = __float2half(vacc[mt][nt][hc * 2 + 1] + qkv_b[257 + G]);
                    }
                }
            }
    }
    __syncthreads();

    // ================= Phase S: scores + softmax (in regs) =================
    const int h = warp >> 1, mh = warp & 1;
    float sacc[2][7][4];
    {
        #pragma unroll
        for (int m = 0; m < 2; m++)
            #pragma unroll
            for (int n = 0; n < 7; n++)
                #pragma unroll
                for (int c = 0; c < 4; c++) sacc[m][n][c] = 0.f;
        #pragma unroll
        for (int kt = 0; kt < 2; kt++) {
            unsigned a[2][4];
            #pragma unroll
            for (int m = 0; m < 2; m++)
                ldm4(a[m], smu + 4u * (QOFF + h * 64 * 20 + ((mh * 2 + m) * 16 + lrow) * 20 + kt * 8 + kwo));
            #pragma unroll
            for (int n = 0; n < 7; n++) {
                unsigned bb[2];
                ldm2(bb, smu + 4u * (KOFF + h * 56 * 20 + (n * 8 + brow) * 20 + kt * 8 + bkwo));
                mma16(sacc[0][n], a[0], bb);
                mma16(sacc[1][n], a[1], bb);
            }
        }
        const float* fus = g_fused + (((b & 63) * 4 + h) * 49) * 56;
        #pragma unroll
        for (int m = 0; m < 2; m++)
            #pragma unroll
            for (int hc = 0; hc < 2; hc++) {
                int row = (mh * 2 + m) * 16 + g + hc * 8;
                float vals[14]; float vmax = -1e30f;
                #pragma unroll
                for (int n = 0; n < 7; n++) {
                    int j = n * 8 + 2 * tg;
                    float f0 = 0.f, f1 = 0.f;
                    if (row < 49) {
                        float2 fv = *(const float2*)&fus[row * 56 + j];
                        f0 = fv.x; f1 = fv.y;
                    }
                    float v0 = (j < 49)     ? sacc[m][n][hc * 2]     + f0 : -1e30f;
                    float v1 = (j + 1 < 49) ? sacc[m][n][hc * 2 + 1] + f1 : -1e30f;
                    if (row >= 49) { v0 = (j < 49) ? 0.f : -1e30f; v1 = (j + 1 < 49) ? 0.f : -1e30f; }
                    vals[2 * n] = v0; vals[2 * n + 1] = v1;
                    vmax = fmaxf(vmax, fmaxf(v0, v1));
                }
                vmax = fmaxf(vmax, __shfl_xor_sync(0xffffffffu, vmax, 1));
                vmax = fmaxf(vmax, __shfl_xor_sync(0xffffffffu, vmax, 2));
                float s = 0.f;
                #pragma unroll
                for (int t = 0; t < 14; t++) { vals[t] = __expf(vals[t] - vmax); s += vals[t]; }
                s += __shfl_xor_sync(0xffffffffu, s, 1);
                s += __shfl_xor_sync(0xffffffffu, s, 2);
                float inv = 1.f / s;
                #pragma unroll
                for (int n = 0; n < 7; n++) {
                    sacc[m][n][hc * 2]     = vals[2 * n] * inv;
                    sacc[m][n][hc * 2 + 1] = vals[2 * n + 1] * inv;
                }
            }
    }
    __syncthreads();   // Q/K reads done before P overlays them
    {
        for (int i = tid; i < 1024; i += 256) {
            int rr = i >> 2, w = 28 + (i & 3);
            sm[POFF + rr * 36 + w] = 0;
        }
        #pragma unroll
        for (int m = 0; m < 2; m++)
            #pragma unroll
            for (int hc = 0; hc < 2; hc++) {
                int row = (mh * 2 + m) * 16 + g + hc * 8;
                #pragma unroll
                for (int n = 0; n < 7; n++) {
                    sm[POFF + (h * 64 + row) * 36 + n * 4 + tg] =
                        f2h2(sacc[m][n][hc * 2], sacc[m][n][hc * 2 + 1]);
                }
            }
    }
    __syncthreads();

    // ================= Phase AV: AO = P @ V (V^T in region 1) =================
    {
        float av[2][4][4];
        #pragma unroll
        for (int m = 0; m < 2; m++)
            #pragma unroll
            for (int n = 0; n < 4; n++)
                #pragma unroll
                for (int c = 0; c < 4; c++) av[m][n][c] = 0.f;
        #pragma unroll
        for (int kt = 0; kt < 4; kt++) {
            unsigned a[2][4];
            #pragma unroll
            for (int m = 0; m < 2; m++)
                ldm4(a[m], smu + 4u * (POFF + h * 64 * 36 + ((mh * 2 + m) * 16 + lrow) * 36 + kt * 8 + kwo));
            #pragma unroll
            for (int n = 0; n < 4; n++) {
                unsigned bb[2];
                ldm2(bb, smu + 4u * (VTOFF + h * 32 * 36 + (n * 8 + brow) * 36 + kt * 8 + bkwo));
                mma16(av[0][n], a[0], bb);
                mma16(av[1][n], a[1], bb);
            }
        }
        __syncthreads();   // P / V^T reads done; region 2 becomes AO
        #pragma unroll
        for (int m = 0; m < 2; m++)
            #pragma unroll
            for (int hc = 0; hc < 2; hc++) {
                int row = (mh * 2 + m) * 16 + g + hc * 8;
                if (row < 49) {
                    #pragma unroll
                    for (int n = 0; n < 4; n++) {
                        sm[AOOFF + row * 68 + h * 16 + n * 4 + tg] =
                            f2h2(av[m][n][hc * 2], av[m][n][hc * 2 + 1]);
                    }
                }
            }
    }
    __syncthreads();

    // ================= Phase E: out = AO @ Wproj + b =================
    {
        float pc[4][2][4];
        #pragma unroll
        for (int mt = 0; mt < 4; mt++)
            #pragma unroll
            for (int n = 0; n < 2; n++)
                #pragma unroll
                for (int c = 0; c < 4; c++) pc[mt][n][c] = 0.f;

        const int colbase = warp * 16;
        unsigned bc[2][2];
        #pragma unroll
        for (int n = 0; n < 2; n++) {
            int col = colbase + n * 8 + g;
            bc[n][0] = g_wprojT[col * 64 + tg];
            bc[n][1] = g_wprojT[col * 64 + tg + 4];
        }
        #pragma unroll
        for (int kt = 0; kt < 8; kt++) {
            unsigned bn[2][2];
            if (kt < 7) {
                int k0 = (kt + 1) * 8;
                #pragma unroll
                for (int n = 0; n < 2; n++) {
                    int col = colbase + n * 8 + g;
                    bn[n][0] = g_wprojT[col * 64 + k0 + tg];
                    bn[n][1] = g_wprojT[col * 64 + k0 + tg + 4];
                }
            }
            unsigned a[4][4];
            #pragma unroll
            for (int mt = 0; mt < 4; mt++)
                ldm4(a[mt], smu + 4u * (AOOFF + (mt * 16 + lrow) * 68 + kt * 8 + kwo));
            #pragma unroll
            for (int mt = 0; mt < 4; mt++)
                #pragma unroll
                for (int n = 0; n < 2; n++) mma16(pc[mt][n], a[mt], bc[n]);
            if (kt < 7) {
                #pragma unroll
                for (int n = 0; n < 2; n++) { bc[n][0] = bn[n][0]; bc[n][1] = bn[n][1]; }
            }
        }
        float* ob = out + (size_t)b * 6272;
        #pragma unroll
        for (int mt = 0; mt < 4; mt++)
            #pragma unroll
            for (int hc = 0; hc < 2; hc++) {
                int row = mt * 16 + g + hc * 8;
                if (row < 49) {
                    #pragma unroll
                    for (int n = 0; n < 2; n++) {
                        int col = colbase + n * 8 + 2 * tg;
                        float2 v;
                        v.x = pc[mt][n][hc * 2]     + proj_b[col];
                        v.y = pc[mt][n][hc * 2 + 1] + proj_b[col + 1];
                        *(float2*)&ob[row * 128 + col] = v;
                    }
                }
            }
    }
}

extern "C" void kernel_launch(void* const* d_in, const int* in_sizes, int n_in,
                              void* d_out, int out_size)
{
    const float* x        = (const float*)d_in[0];
    const float* mask     = (const float*)d_in[1];
    const float* qkv_w    = (const float*)d_in[2];
    const float* qkv_b    = (const float*)d_in[3];
    const float* proj_w   = (const float*)d_in[4];
    const float* proj_b   = (const float*)d_in[5];
    const float* bias_tab = (const float*)d_in[6];
    float* out = (float*)d_out;

    cudaFuncSetAttribute(win_attn_mma,
                         cudaFuncAttributeMaxDynamicSharedMemorySize,
                         SMEM_WORDS * 4);

    prep_kernel<<<512, 256>>>(mask, bias_tab, qkv_w, proj_w);
    win_attn_mma<<<4096, 256, SMEM_WORDS * 4>>>(x, qkv_b, proj_b, out);
}